// round 8
// baseline (speedup 1.0000x reference)
#include <cuda_runtime.h>
#include <cstdint>

// Problem constants (fixed shapes from reference)
#define SN 2048
#define DN 16
#define BHN 16   // B*H = 2*8
#define NKT 16   // SN/128 k-tiles

// Scratch (no cudaMalloc allowed): ~33 KB
__device__ float g_WuPart[BHN][NKT][DN][DN]; // per-k-slice partial K'xV
__device__ float g_MvPart[BHN][NKT][DN];     // per-k-slice partial masked-V sum

static __device__ __forceinline__ float tf32_rna(float x) {
    unsigned u;
    asm("cvt.rna.tf32.f32 %0, %1;" : "=r"(u) : "f"(x));
    return __uint_as_float(u);
}

static __device__ __forceinline__ void mma_tf32(
    float& c0, float& c1, float& c2, float& c3,
    unsigned a0, unsigned a1, unsigned a2, unsigned a3,
    unsigned b0, unsigned b1) {
    asm volatile(
        "mma.sync.aligned.m16n8k8.row.col.f32.tf32.tf32.f32 "
        "{%0,%1,%2,%3}, {%4,%5,%6,%7}, {%8,%9}, {%0,%1,%2,%3};"
        : "+f"(c0), "+f"(c1), "+f"(c2), "+f"(c3)
        : "r"(a0), "r"(a1), "r"(a2), "r"(a3), "r"(b0), "r"(b1));
}

// ---------------------------------------------------------------------------
// Kernel W: Wu/Mv partials per 128-k slice. grid(NKT, BH)
// ---------------------------------------------------------------------------
__global__ __launch_bounds__(256) void wu_kernel(
    const float* __restrict__ K, const float* __restrict__ V,
    const void* __restrict__ mask) {
    int bh = blockIdx.y;
    int k0 = blockIdx.x * 128;
    __shared__ float sK[DN][132];
    __shared__ float sV[128][17];
    __shared__ unsigned char sM[128];
    __shared__ int sIsI32;
    int t = threadIdx.x;

    if (t == 0) {
        const int* m = (const int*)mask;
        int ok = 1;
        #pragma unroll
        for (int i = 0; i < 64; i++) {
            int v = m[i];
            if (v != 0 && v != 1) ok = 0;
        }
        sIsI32 = ok;
    }
    __syncthreads();
    if (t < 128) {
        size_t idx = ((size_t)bh * SN + (SN - 1)) * SN + k0 + t;
        int mv = sIsI32 ? ((const int*)mask)[idx]
                        : (int)((const unsigned char*)mask)[idx];
        sM[t] = (unsigned char)(mv != 0);
    }
    __syncthreads();
    const float* Kb = K + (size_t)bh * SN * DN;
    const float* Vb = V + (size_t)bh * SN * DN;
    for (int i = t; i < 128 * DN; i += 256) {
        int r = i / DN, d = i % DN;
        sK[d][r] = sM[r] ? 0.f : Kb[(size_t)(k0 + r) * DN + d] * 0.25f;
        sV[r][d] = Vb[(size_t)(k0 + r) * DN + d];
    }
    __syncthreads();
    {
        int i = t / DN, j = t % DN;
        float acc = 0.f;
        #pragma unroll 8
        for (int k = 0; k < 128; k++) acc += sK[i][k] * sV[k][j];
        g_WuPart[bh][blockIdx.x][i][j] = acc;
    }
    if (t < DN) {
        float a = 0.f;
        for (int k = 0; k < 128; k++)
            if (sM[k]) a += sV[k][t];
        g_MvPart[bh][blockIdx.x][t] = a;
    }
}

// ---------------------------------------------------------------------------
// Kernel B: reduce partials, then context = Q*Wu - 1e9*Mv.  grid(16, BH)
// ---------------------------------------------------------------------------
__global__ __launch_bounds__(256) void ctx_kernel(
    const float* __restrict__ Q, float* __restrict__ out) {
    int bh = blockIdx.y;
    int q0 = blockIdx.x * 128;
    __shared__ float sW[DN][DN];
    __shared__ float sMv[DN];
    __shared__ float sQ[128][17];
    int t = threadIdx.x;

    if (t < DN * DN) {
        float a = 0.f;
        #pragma unroll
        for (int s = 0; s < NKT; s++)
            a += ((const float*)g_WuPart[bh][s])[t];
        ((float*)sW)[t] = a;
    }
    if (t < DN) {
        float a = 0.f;
        #pragma unroll
        for (int s = 0; s < NKT; s++) a += g_MvPart[bh][s][t];
        sMv[t] = a;
    }
    const float* Qb = Q + (size_t)bh * SN * DN;
    for (int i = t; i < 128 * DN; i += 256) {
        int r = i / DN, d = i % DN;
        sQ[r][d] = Qb[(size_t)(q0 + r) * DN + d];
    }
    __syncthreads();

    for (int i = t; i < 128 * DN; i += 256) {
        int q = i / DN, d = i % DN;
        float acc = -1e9f * sMv[d];
        #pragma unroll
        for (int ii = 0; ii < DN; ii++) acc += sQ[q][ii] * sW[ii][d];
        out[((size_t)bh * SN + q0 + q) * DN + d] = acc;
    }
}

// ---------------------------------------------------------------------------
// Kernel C: scores via tf32 tensor cores, 3-term Dekker split.
// Block 128q x 128k, 256 threads (8 warps). Warp w: rows [w*16, w*16+16).
// Per warp: 16 n-tiles x 2 d-chunks x 3 mma(m16n8k8.tf32).
// smem tiles [split][row][d] padded to 20 floats -> conflict-free frag LDS.
// grid(SN/128, SN/128, BH)
// ---------------------------------------------------------------------------
__global__ __launch_bounds__(256, 2) void scores_kernel(
    const float* __restrict__ Q, const float* __restrict__ K,
    const void* __restrict__ mask, float* __restrict__ out) {
    int bh = blockIdx.z;
    int q0 = blockIdx.y * 128;
    int k0 = blockIdx.x * 128;

    __shared__ float sQ[2][128][20];   // [hi/lo][q][d]
    __shared__ float sK[2][128][20];   // [hi/lo][k][d], masked * 0.25
    __shared__ float sB[128];
    __shared__ unsigned char sM[128];
    __shared__ int sIsI32;
    int t = threadIdx.x;

    if (t == 0) {
        const int* m = (const int*)mask;
        int ok = 1;
        #pragma unroll
        for (int i = 0; i < 64; i++) {
            int v = m[i];
            if (v != 0 && v != 1) ok = 0;
        }
        sIsI32 = ok;
    }

    const float* Qb = Q + (size_t)bh * SN * DN;
    const float* Kb = K + (size_t)bh * SN * DN;

    // Q fill (no mask dependency): 512 float4, 2 per thread
    float4 kv[2];
    int rr[2];
    #pragma unroll
    for (int it = 0; it < 2; it++) {
        int i = it * 256 + t;
        int r = i >> 2, c4 = (i & 3) * 4;
        rr[it] = r;
        float4 qv = *(const float4*)&Qb[(size_t)(q0 + r) * DN + c4];
        kv[it]    = *(const float4*)&Kb[(size_t)(k0 + r) * DN + c4];
        float qe[4] = {qv.x, qv.y, qv.z, qv.w};
        #pragma unroll
        for (int j = 0; j < 4; j++) {
            float hi = tf32_rna(qe[j]);
            sQ[0][r][c4 + j] = hi;
            sQ[1][r][c4 + j] = tf32_rna(qe[j] - hi);
        }
    }
    __syncthreads();   // sIsI32 ready

    if (t < 128) {
        size_t idx = ((size_t)bh * SN + (SN - 1)) * SN + k0 + t;
        int mv = sIsI32 ? ((const int*)mask)[idx]
                        : (int)((const unsigned char*)mask)[idx];
        sM[t] = (unsigned char)(mv != 0);
        sB[t] = mv ? -1e9f : 0.f;
    }
    __syncthreads();   // sM ready

    #pragma unroll
    for (int it = 0; it < 2; it++) {
        int i = it * 256 + t;
        int r = rr[it], c4 = (i & 3) * 4;
        float m = sM[r] ? 0.f : 0.25f;
        float ke[4] = {kv[it].x * m, kv[it].y * m, kv[it].z * m, kv[it].w * m};
        #pragma unroll
        for (int j = 0; j < 4; j++) {
            float hi = tf32_rna(ke[j]);
            sK[0][r][c4 + j] = hi;
            sK[1][r][c4 + j] = tf32_rna(ke[j] - hi);
        }
    }
    __syncthreads();

    int lane = t & 31, w = t >> 5;
    int g = lane >> 2, tg = lane & 3;
    int qrow = w * 16 + g;

    // A fragments (resident): a[split][kchunk][4]
    unsigned a[2][2][4];
    #pragma unroll
    for (int s = 0; s < 2; s++)
        #pragma unroll
        for (int kc = 0; kc < 2; kc++) {
            int d = kc * 8 + tg;
            a[s][kc][0] = __float_as_uint(sQ[s][qrow][d]);
            a[s][kc][1] = __float_as_uint(sQ[s][qrow + 8][d]);
            a[s][kc][2] = __float_as_uint(sQ[s][qrow][d + 4]);
            a[s][kc][3] = __float_as_uint(sQ[s][qrow + 8][d + 4]);
        }

    float* orow0 = out + ((size_t)bh * SN + (q0 + qrow)) * (size_t)SN + k0;
    float* orow1 = orow0 + (size_t)8 * SN;

    #pragma unroll
    for (int nt = 0; nt < 16; nt++) {
        int kcol = nt * 8 + g;             // B n-index (k of scores)
        float2 bb = *(const float2*)&sB[nt * 8 + tg * 2];
        float c0 = bb.x, c1 = bb.y, c2 = bb.x, c3 = bb.y;
        #pragma unroll
        for (int kc = 0; kc < 2; kc++) {
            int d = kc * 8 + tg;
            unsigned bh0 = __float_as_uint(sK[0][kcol][d]);
            unsigned bh1 = __float_as_uint(sK[0][kcol][d + 4]);
            unsigned bl0 = __float_as_uint(sK[1][kcol][d]);
            unsigned bl1 = __float_as_uint(sK[1][kcol][d + 4]);
            mma_tf32(c0, c1, c2, c3, a[0][kc][0], a[0][kc][1], a[0][kc][2], a[0][kc][3], bh0, bh1);
            mma_tf32(c0, c1, c2, c3, a[0][kc][0], a[0][kc][1], a[0][kc][2], a[0][kc][3], bl0, bl1);
            mma_tf32(c0, c1, c2, c3, a[1][kc][0], a[1][kc][1], a[1][kc][2], a[1][kc][3], bh0, bh1);
        }
        int co = nt * 8 + tg * 2;
        *(float2*)&orow0[co] = make_float2(c0, c1);
        *(float2*)&orow1[co] = make_float2(c2, c3);
    }
}

// ---------------------------------------------------------------------------
extern "C" void kernel_launch(void* const* d_in, const int* in_sizes, int n_in,
                              void* d_out, int out_size) {
    const float* Q = (const float*)d_in[0];
    const float* K = (const float*)d_in[1];
    const float* V = (const float*)d_in[2];
    const void*  mask = d_in[3];
    float* out = (float*)d_out;

    const long long ctx_elems = (long long)BHN * SN * DN;        // 524288
    const long long sc_elems  = (long long)BHN * SN * SN;        // 67108864

    float* ctx_out = nullptr;
    float* sc_out  = nullptr;
    if ((long long)out_size >= ctx_elems + sc_elems) {
        ctx_out = out;
        sc_out  = out + ctx_elems;
    } else if ((long long)out_size == sc_elems) {
        sc_out = out;
    } else {
        ctx_out = out;
    }

    if (ctx_out) {
        dim3 g(NKT, BHN);
        wu_kernel<<<g, 256>>>(K, V, mask);
        dim3 g2(SN / 128, BHN);
        ctx_kernel<<<g2, 256>>>(Q, ctx_out);
    }
    if (sc_out) {
        dim3 g(SN / 128, SN / 128, BHN);
        scores_kernel<<<g, 256>>>(Q, K, mask, sc_out);
    }
}

// round 9
// speedup vs baseline: 1.3562x; 1.3562x over previous
#include <cuda_runtime.h>
#include <cstdint>

// Problem constants (fixed shapes from reference)
#define SN 2048
#define DN 16
#define BHN 16   // B*H = 2*8
#define NSL 64   // SN/32 prep slices

// Scratch (no cudaMalloc allowed)
__device__ float g_Kt[BHN][DN][SN];          // K transposed, masked->0, *0.25
__device__ float g_Qt[BHN][DN][SN];          // Q transposed
__device__ float g_bias[BHN][SN];            // mask ? -1e9 : 0
__device__ float g_WuPart[BHN][NSL][DN][DN]; // per-slice partial K'xV
__device__ float g_MvPart[BHN][NSL][DN];     // per-slice partial masked-V sum

static __device__ __forceinline__ unsigned long long ffma2(
    unsigned long long a, unsigned long long b, unsigned long long c) {
    unsigned long long d;
    asm("fma.rn.f32x2 %0, %1, %2, %3;" : "=l"(d) : "l"(a), "l"(b), "l"(c));
    return d;
}
static __device__ __forceinline__ unsigned long long pack2(float x) {
    unsigned long long r;
    asm("mov.b64 %0, {%1, %2};" : "=l"(r) : "f"(x), "f"(x));
    return r;
}

// ---------------------------------------------------------------------------
// Kernel A: per-head prep, 32-row slices (short chains, many waves).
// Detects mask dtype per block (int32 0/1 words vs packed bytes;
// P(false positive) ~ 8^-64). Transposes Q,K; folds mask+0.25 into K';
// bias; per-slice Wu/Mv partials with 4 accumulators. grid(NSL, BH)
// ---------------------------------------------------------------------------
__global__ __launch_bounds__(256) void prep_kernel(
    const float* __restrict__ Q, const float* __restrict__ K,
    const float* __restrict__ V, const void* __restrict__ mask) {
    int bh = blockIdx.y;
    int sl = blockIdx.x;
    int c0 = sl * 32;
    __shared__ float sK[32][17];
    __shared__ float sV[32][17];
    __shared__ float sQ[32][17];
    __shared__ unsigned char sM[32];
    __shared__ int sIsI32;
    int t = threadIdx.x;

    if (t == 0) {
        const int* m = (const int*)mask;
        int ok = 1;
        #pragma unroll
        for (int i = 0; i < 64; i++) {
            int v = m[i];
            if (v != 0 && v != 1) ok = 0;
        }
        sIsI32 = ok;
    }

    const float* Kb = K + (size_t)bh * SN * DN;
    const float* Vb = V + (size_t)bh * SN * DN;
    const float* Qb = Q + (size_t)bh * SN * DN;

    // 32 rows x 16 d = 512 elems; 256 threads -> 2 per thread per array
    #pragma unroll
    for (int it = 0; it < 2; it++) {
        int i = it * 256 + t;
        int r = i / DN, d = i % DN;
        sK[r][d] = Kb[(size_t)(c0 + r) * DN + d];
        sV[r][d] = Vb[(size_t)(c0 + r) * DN + d];
        sQ[r][d] = Qb[(size_t)(c0 + r) * DN + d];
    }
    __syncthreads();   // sIsI32 ready
    if (t < 32) {
        size_t idx = ((size_t)bh * SN + (SN - 1)) * SN + c0 + t;
        int mv = sIsI32 ? ((const int*)mask)[idx]
                        : (int)((const unsigned char*)mask)[idx];
        sM[t] = (unsigned char)(mv != 0);
    }
    __syncthreads();   // sM ready

    // transposed writes: 16 d-rows x 32 cols; 128B coalesced per d-row
    #pragma unroll
    for (int it = 0; it < 2; it++) {
        int i = it * 256 + t;
        int d = i / 32, k = i % 32;
        float kv = sM[k] ? 0.f : sK[k][d] * 0.25f;
        g_Kt[bh][d][c0 + k] = kv;
        sK[k][d] = kv;
        g_Qt[bh][d][c0 + k] = sQ[k][d];
    }
    if (t < 32) g_bias[bh][c0 + t] = sM[t] ? -1e9f : 0.f;
    __syncthreads();

    // Wu partial: 32 k-iters, 4 independent accumulators (chain depth 8)
    {
        int i = t / DN, j = t % DN;
        float a0 = 0.f, a1 = 0.f, a2 = 0.f, a3 = 0.f;
        #pragma unroll
        for (int k = 0; k < 32; k += 4) {
            a0 += sK[k + 0][i] * sV[k + 0][j];
            a1 += sK[k + 1][i] * sV[k + 1][j];
            a2 += sK[k + 2][i] * sV[k + 2][j];
            a3 += sK[k + 3][i] * sV[k + 3][j];
        }
        g_WuPart[bh][sl][i][j] = (a0 + a1) + (a2 + a3);
    }
    if (t < DN) {
        float a0 = 0.f, a1 = 0.f;
        #pragma unroll
        for (int k = 0; k < 32; k += 2) {
            if (sM[k])     a0 += sV[k][t];
            if (sM[k + 1]) a1 += sV[k + 1][t];
        }
        g_MvPart[bh][sl][t] = a0 + a1;
    }
}

// ---------------------------------------------------------------------------
// Kernel B: reduce partials (4 accs, independent LDGs), then
// context = Q*Wu - 1e9*Mv.  grid(16, BH)
// ---------------------------------------------------------------------------
__global__ __launch_bounds__(256) void ctx_kernel(
    const float* __restrict__ Q, float* __restrict__ out) {
    int bh = blockIdx.y;
    int q0 = blockIdx.x * 128;
    __shared__ float sW[DN][DN];
    __shared__ float sMv[DN];
    __shared__ float sQ[128][17];
    int t = threadIdx.x;

    if (t < DN * DN) {
        float a0 = 0.f, a1 = 0.f, a2 = 0.f, a3 = 0.f;
        #pragma unroll
        for (int s = 0; s < NSL; s += 4) {
            a0 += ((const float*)g_WuPart[bh][s + 0])[t];
            a1 += ((const float*)g_WuPart[bh][s + 1])[t];
            a2 += ((const float*)g_WuPart[bh][s + 2])[t];
            a3 += ((const float*)g_WuPart[bh][s + 3])[t];
        }
        ((float*)sW)[t] = (a0 + a1) + (a2 + a3);
    }
    if (t < DN) {
        float a0 = 0.f, a1 = 0.f;
        #pragma unroll
        for (int s = 0; s < NSL; s += 2) {
            a0 += g_MvPart[bh][s + 0][t];
            a1 += g_MvPart[bh][s + 1][t];
        }
        sMv[t] = a0 + a1;
    }
    const float* Qb = Q + (size_t)bh * SN * DN;
    for (int i = t; i < 128 * DN; i += 256) {
        int r = i / DN, d = i % DN;
        sQ[r][d] = Qb[(size_t)(q0 + r) * DN + d];
    }
    __syncthreads();

    for (int i = t; i < 128 * DN; i += 256) {
        int q = i / DN, d = i % DN;
        float acc = -1e9f * sMv[d];
        #pragma unroll
        for (int ii = 0; ii < DN; ii++) acc += sQ[q][ii] * sW[ii][d];
        out[((size_t)bh * SN + q0 + q) * DN + d] = acc;
    }
}

// ---------------------------------------------------------------------------
// Kernel C: the 268 MB scores tensor — proven R3/R6 configuration (64.8us).
// Block tile 128q x 128k, 256 threads (8 warps, 4x2), thread tile 8q x 8k.
// score = bias[k] + dot(Q[q,:], K'[k,:]) via packed fp32x2 FMA (k-pairs).
// grid(SN/128, SN/128, BH)
// ---------------------------------------------------------------------------
__global__ __launch_bounds__(256, 2) void scores_kernel(float* __restrict__ out) {
    int bh = blockIdx.z;
    int q0 = blockIdx.y * 128;
    int k0 = blockIdx.x * 128;

    __shared__ float sQ[DN][128];
    __shared__ float sK[DN][128];
    __shared__ float sB[128];
    int t = threadIdx.x;

    const float* Qt = &g_Qt[bh][0][0];
    const float* Kt = &g_Kt[bh][0][0];
    #pragma unroll
    for (int it = 0; it < 2; it++) {
        int i = it * 256 + t;          // float4 index, 0..511
        int d = i / 32, c = i % 32;
        *(float4*)&sQ[d][c * 4] = *(const float4*)&Qt[(size_t)d * SN + q0 + c * 4];
        *(float4*)&sK[d][c * 4] = *(const float4*)&Kt[(size_t)d * SN + k0 + c * 4];
    }
    if (t < 32) *(float4*)&sB[t * 4] = *(const float4*)&g_bias[bh][k0 + t * 4];
    __syncthreads();

    int lane = t & 31, wid = t >> 5;
    int wq = wid >> 1, wk = wid & 1;   // 4 q-warps x 2 k-warps
    int lq = lane >> 3, lk = lane & 7;
    int qb = wq * 32 + lq * 8;         // 8 q rows
    int kb = wk * 64 + lk * 4;         // 4 k (group0); group1 at +32

    unsigned long long acc[8][4];
    {
        unsigned long long b0 = *(const unsigned long long*)&sB[kb];
        unsigned long long b1 = *(const unsigned long long*)&sB[kb + 2];
        unsigned long long b2 = *(const unsigned long long*)&sB[kb + 32];
        unsigned long long b3 = *(const unsigned long long*)&sB[kb + 34];
        #pragma unroll
        for (int iq = 0; iq < 8; iq++) {
            acc[iq][0] = b0; acc[iq][1] = b1; acc[iq][2] = b2; acc[iq][3] = b3;
        }
    }

    #pragma unroll
    for (int d = 0; d < DN; d++) {
        float4 qa = *(const float4*)&sQ[d][qb];
        float4 qc = *(const float4*)&sQ[d][qb + 4];
        unsigned long long av[8];
        av[0] = pack2(qa.x); av[1] = pack2(qa.y); av[2] = pack2(qa.z); av[3] = pack2(qa.w);
        av[4] = pack2(qc.x); av[5] = pack2(qc.y); av[6] = pack2(qc.z); av[7] = pack2(qc.w);
        const unsigned long long* kp0 = (const unsigned long long*)&sK[d][kb];
        const unsigned long long* kp1 = (const unsigned long long*)&sK[d][kb + 32];
        unsigned long long b0 = kp0[0], b1 = kp0[1];
        unsigned long long b2 = kp1[0], b3 = kp1[1];
        #pragma unroll
        for (int iq = 0; iq < 8; iq++) {
            acc[iq][0] = ffma2(av[iq], b0, acc[iq][0]);
            acc[iq][1] = ffma2(av[iq], b1, acc[iq][1]);
            acc[iq][2] = ffma2(av[iq], b2, acc[iq][2]);
            acc[iq][3] = ffma2(av[iq], b3, acc[iq][3]);
        }
    }

    #pragma unroll
    for (int iq = 0; iq < 8; iq++) {
        float* row = out + ((size_t)bh * SN + (q0 + qb + iq)) * (size_t)SN + k0;
        ulonglong2 v0; v0.x = acc[iq][0]; v0.y = acc[iq][1];
        ulonglong2 v1; v1.x = acc[iq][2]; v1.y = acc[iq][3];
        *(ulonglong2*)(row + kb) = v0;
        *(ulonglong2*)(row + kb + 32) = v1;
    }
}

// ---------------------------------------------------------------------------
extern "C" void kernel_launch(void* const* d_in, const int* in_sizes, int n_in,
                              void* d_out, int out_size) {
    const float* Q = (const float*)d_in[0];
    const float* K = (const float*)d_in[1];
    const float* V = (const float*)d_in[2];
    const void*  mask = d_in[3];
    float* out = (float*)d_out;

    const long long ctx_elems = (long long)BHN * SN * DN;        // 524288
    const long long sc_elems  = (long long)BHN * SN * SN;        // 67108864

    float* ctx_out = nullptr;
    float* sc_out  = nullptr;
    if ((long long)out_size >= ctx_elems + sc_elems) {
        ctx_out = out;
        sc_out  = out + ctx_elems;
    } else if ((long long)out_size == sc_elems) {
        sc_out = out;
    } else {
        ctx_out = out;
    }

    {
        dim3 g(NSL, BHN);
        prep_kernel<<<g, 256>>>(Q, K, V, mask);
    }
    if (ctx_out) {
        dim3 g(SN / 128, BHN);
        ctx_kernel<<<g, 256>>>(Q, ctx_out);
    }
    if (sc_out) {
        dim3 g(SN / 128, SN / 128, BHN);
        scores_kernel<<<g, 256>>>(sc_out);
    }
}